// round 7
// baseline (speedup 1.0000x reference)
#include <cuda_runtime.h>
#include <stdint.h>

#define NPTS 500000
#define KK 27

// Scratch (allocation-free rule: __device__ globals)
__device__ float g_h0 [NPTS * 32];
__device__ float g_h0c[NPTS * 32];
__device__ float g_h1 [NPTS * 32];

// Permuted tf32 weights, fragment-ordered, channel-consecutive:
//   slot s = ((k*PAIRS + pr)*NTS + nt)*32 + lane, uint4 =
//   { W[k][pr*16+four*4+j][nt*8+grp] : j=0..3 }  (four=lane&3, grp=lane>>2)
// uint4 counts: W10 27*8*4*32=27648, W01 27*2*4*32=6912, W11 27*2*8*32=13824,
//               W00 1*8*4*32=1024,   W02 1*2*8*32=512
#define WP10_OFF 0
#define WP01_OFF 27648
#define WP11_OFF (27648 + 6912)
#define WP00_OFF (27648 + 6912 + 13824)
#define WP02_OFF (27648 + 6912 + 13824 + 1024)
__device__ uint4 g_wperm[27648 + 6912 + 13824 + 1024 + 512];

// ---------------------------------------------------------------------------
__device__ __forceinline__ uint32_t f2tf32(float v) {
    uint32_t r;
    asm("cvt.rna.tf32.f32 %0, %1;" : "=r"(r) : "f"(v));
    return r;
}

__device__ __forceinline__ void mma_16n8k8(float* c, uint32_t a0, uint32_t a1,
                                           uint32_t a2, uint32_t a3,
                                           uint32_t b0, uint32_t b1) {
    asm volatile(
        "mma.sync.aligned.m16n8k8.row.col.f32.tf32.tf32.f32 "
        "{%0,%1,%2,%3}, {%4,%5,%6,%7}, {%8,%9}, {%0,%1,%2,%3};"
        : "+f"(c[0]), "+f"(c[1]), "+f"(c[2]), "+f"(c[3])
        : "r"(a0), "r"(a1), "r"(a2), "r"(a3), "r"(b0), "r"(b1));
}

// ---------------------------------------------------------------------------
// Weight permutation prep. K-permutation: within each 16-channel block,
// mma k-slot s holds channel 4*(s&3) + (s>>2); equivalently the uint4 for
// lane (four) at (pr,nt) holds channels pr*16 + four*4 + {0,1,2,3}.
// A-side then loads ONE float4 per row-chunk.
// ---------------------------------------------------------------------------
template <int CIN, int COUT, int KKT>
__global__ void k_permW(const float* __restrict__ W, uint4* __restrict__ dst)
{
    const int PAIRS = CIN / 16, NTS = COUT / 8;
    const int total = KKT * PAIRS * NTS * 32;
    const int s = blockIdx.x * 256 + threadIdx.x;
    if (s >= total) return;
    const int lane = s & 31;
    int t = s >> 5;
    const int nt = t % NTS; t /= NTS;
    const int pr = t % PAIRS; t /= PAIRS;
    const int k = t;
    const int four = lane & 3, grp = lane >> 2;
    const int col = nt * 8 + grp;
    const int c0 = pr * 16 + four * 4;
    const size_t base = (size_t)k * CIN * COUT + col;
    uint4 v;
    v.x = f2tf32(W[base + (size_t)(c0 + 0) * COUT]);
    v.y = f2tf32(W[base + (size_t)(c0 + 1) * COUT]);
    v.z = f2tf32(W[base + (size_t)(c0 + 2) * COUT]);
    v.w = f2tf32(W[base + (size_t)(c0 + 3) * COUT]);
    dst[s] = v;
}

// ---------------------------------------------------------------------------
// Unified sparse-conv GEMM via mma.sync tf32.
// Block: 256 threads = 8 warps; 256 points/block; warp owns 32 points
// (two m16 tiles).  GATHER=1: 27-tap gather conv (nbr/mask).  GATHER=0: 1x1.
// MODE 0: out[N,COUT] = relu(acc + b)
// MODE 1: out[N,128] cols [64,128) = acc + b + x[:,64:128)   (COUT=64)
// MODE 2: out[N,128] cols [0,64)   = acc + b + x[:,0:64)     (COUT=64)
// ---------------------------------------------------------------------------
template <int CIN, int COUT, int MODE, int GATHER>
__global__ __launch_bounds__(256) void k_conv_mma(
    const float* __restrict__ f, const int* __restrict__ nbr,
    const int* __restrict__ mask, const uint4* __restrict__ Wp,
    const float* __restrict__ b, const float* __restrict__ x,
    float* __restrict__ out)
{
    const int PAIRS = CIN / 16, NTS = COUT / 8;
    const int KT = GATHER ? KK : 1;
    __shared__ int   midx[GATHER ? 256 * KK : 8];
    __shared__ uint4 Bs4[CIN * COUT / 4];
    __shared__ float bs[COUT];

    const int tid  = threadIdx.x;
    const int warp = tid >> 5;
    const int lane = tid & 31;
    const int grp  = lane >> 2;
    const int four = lane & 3;

    if (tid < COUT) bs[tid] = b[tid];

    const int pbase = blockIdx.x * 256;
    if (GATHER) {
        for (int i = tid; i < 256 * KK; i += 256) {
            const int p = pbase + i / KK;
            int v = -1;
            if (p < NPTS) {
                const size_t g = (size_t)p * KK + (i % KK);
                if (mask[g] != 0) v = nbr[g];
            }
            midx[i] = v;
        }
    }

    const int lr = warp * 32 + grp;          // rows lr+{0,8,16,24}

    float acc0[NTS][4], acc1[NTS][4];
#pragma unroll
    for (int nt = 0; nt < NTS; nt++)
#pragma unroll
        for (int j = 0; j < 4; j++) { acc0[nt][j] = 0.f; acc1[nt][j] = 0.f; }

    const int slabN = PAIRS * NTS * 32;      // uint4 per k

    for (int k = 0; k < KT; k++) {
        __syncthreads();
        for (int i = tid; i < slabN; i += 256)
            Bs4[i] = Wp[(size_t)k * slabN + i];
        __syncthreads();

        int idx[4];
#pragma unroll
        for (int r = 0; r < 4; r++) {
            if (GATHER) {
                idx[r] = midx[(lr + r * 8) * KK + k];
            } else {
                const int p = pbase + lr + r * 8;
                idx[r] = (p < NPTS) ? p : (NPTS - 1);   // clamp; store guarded later
            }
        }
        const float* rows[4];
#pragma unroll
        for (int r = 0; r < 4; r++)
            rows[r] = f + (size_t)(idx[r] < 0 ? 0 : idx[r]) * CIN;

#pragma unroll
        for (int pr = 0; pr < PAIRS; pr++) {
            uint32_t A[4][4];
#pragma unroll
            for (int r = 0; r < 4; r++) {
                if (!GATHER || idx[r] >= 0) {
                    const float4 q = *reinterpret_cast<const float4*>(
                        rows[r] + pr * 16 + four * 4);
                    A[r][0] = f2tf32(q.x);
                    A[r][1] = f2tf32(q.y);
                    A[r][2] = f2tf32(q.z);
                    A[r][3] = f2tf32(q.w);
                } else {
                    A[r][0] = A[r][1] = A[r][2] = A[r][3] = 0u;
                }
            }
#pragma unroll
            for (int nt = 0; nt < NTS; nt++) {
                const uint4 B = Bs4[(pr * NTS + nt) * 32 + lane];
                mma_16n8k8(acc0[nt], A[0][0], A[1][0], A[0][1], A[1][1], B.x, B.y);
                mma_16n8k8(acc0[nt], A[0][2], A[1][2], A[0][3], A[1][3], B.z, B.w);
                mma_16n8k8(acc1[nt], A[2][0], A[3][0], A[2][1], A[3][1], B.x, B.y);
                mma_16n8k8(acc1[nt], A[2][2], A[3][2], A[2][3], A[3][3], B.z, B.w);
            }
        }
    }

    // epilogue: acc0 -> rows lr, lr+8 ; acc1 -> rows lr+16, lr+24
#pragma unroll
    for (int t = 0; t < 2; t++) {
#pragma unroll
        for (int half = 0; half < 2; half++) {
            const int p = pbase + lr + t * 16 + half * 8;
            if (p >= NPTS) continue;
#pragma unroll
            for (int nt = 0; nt < NTS; nt++) {
                const float c0 = (t == 0) ? acc0[nt][half * 2]     : acc1[nt][half * 2];
                const float c1 = (t == 0) ? acc0[nt][half * 2 + 1] : acc1[nt][half * 2 + 1];
                const int col = nt * 8 + 2 * four;
                if (MODE == 0) {
                    float2 v = {fmaxf(c0 + bs[col], 0.f), fmaxf(c1 + bs[col + 1], 0.f)};
                    *reinterpret_cast<float2*>(out + (size_t)p * COUT + col) = v;
                } else {
                    const int oc = (MODE == 1) ? (64 + col) : col;
                    const size_t a = (size_t)p * 128 + oc;
                    float2 xr = *reinterpret_cast<const float2*>(x + a);
                    float2 v = {c0 + bs[col] + xr.x, c1 + bs[col + 1] + xr.y};
                    *reinterpret_cast<float2*>(out + a) = v;
                }
            }
        }
    }
}

// ---------------------------------------------------------------------------
extern "C" void kernel_launch(void* const* d_in, const int* in_sizes, int n_in,
                              void* d_out, int out_size)
{
    const float* x    = (const float*)d_in[0];
    const int*   nbr  = (const int*)  d_in[1];
    const int*   mask = (const int*)  d_in[2];   // bool -> int32 in harness
    const float* W00  = (const float*)d_in[3];
    const float* b00  = (const float*)d_in[4];
    const float* W01  = (const float*)d_in[5];
    const float* b01  = (const float*)d_in[6];
    const float* W02  = (const float*)d_in[7];
    const float* b02  = (const float*)d_in[8];
    const float* W10  = (const float*)d_in[9];
    const float* b10  = (const float*)d_in[10];
    const float* W11  = (const float*)d_in[11];
    const float* b11  = (const float*)d_in[12];
    float* out = (float*)d_out;

    float *h0, *h0c, *h1;
    uint4* wp;
    cudaGetSymbolAddress((void**)&h0,  g_h0);
    cudaGetSymbolAddress((void**)&h0c, g_h0c);
    cudaGetSymbolAddress((void**)&h1,  g_h1);
    cudaGetSymbolAddress((void**)&wp,  g_wperm);

    // weight permutation (tiny)
    k_permW<128, 32, KK><<<(27648 + 255) / 256, 256>>>(W10, wp + WP10_OFF);
    k_permW< 32, 32, KK><<<( 6912 + 255) / 256, 256>>>(W01, wp + WP01_OFF);
    k_permW< 32, 64, KK><<<(13824 + 255) / 256, 256>>>(W11, wp + WP11_OFF);
    k_permW<128, 32,  1><<<( 1024 + 255) / 256, 256>>>(W00, wp + WP00_OFF);
    k_permW< 32, 64,  1><<<(  512 + 255) / 256, 256>>>(W02, wp + WP02_OFF);

    const int blocks = (NPTS + 255) / 256;

    // branch 0: 1x1 -> relu  (mma, no gather)
    k_conv_mma<128, 32, 0, 0><<<blocks, 256>>>(x, nullptr, nullptr, wp + WP00_OFF, b00, nullptr, h0);
    // branch 1: 3x3 -> relu
    k_conv_mma<128, 32, 0, 1><<<blocks, 256>>>(x, nbr, mask, wp + WP10_OFF, b10, nullptr, h1);
    // branch 0: 3x3 -> relu
    k_conv_mma<32, 32, 0, 1><<<blocks, 256>>>(h0, nbr, mask, wp + WP01_OFF, b01, nullptr, h0c);
    // branch 0 tail: 1x1 + bias + residual -> out[:, 0:64)
    k_conv_mma<32, 64, 2, 0><<<blocks, 256>>>(h0c, nullptr, nullptr, wp + WP02_OFF, b02, x, out);
    // branch 1 tail: 3x3 + bias + residual -> out[:, 64:128)
    k_conv_mma<32, 64, 1, 1><<<blocks, 256>>>(h1, nbr, mask, wp + WP11_OFF, b11, x, out);
}

// round 8
// speedup vs baseline: 1.6224x; 1.6224x over previous
#include <cuda_runtime.h>
#include <stdint.h>

#define NPTS 500000
#define KK 27

// Scratch (allocation-free rule: __device__ globals)
__device__ float g_h0 [NPTS * 32];
__device__ float g_h0c[NPTS * 32];
__device__ float g_h1 [NPTS * 32];

// Permuted tf32 weights, fragment-ordered (R5 layout):
//   slot s = ((k*PAIRS + pr)*NTS + nt)*32 + lane, each slot = uint4
//   {W[k][pr*16+four][col], W[k][pr*16+four+4][col],
//    W[k][pr*16+four+8][col], W[k][pr*16+four+12][col]}
//   with four=lane&3, grp=lane>>2, col=nt*8+grp.
// uint4 counts: W10 27*8*4*32=27648, W01 27*2*4*32=6912, W11 27*2*8*32=13824,
//               W00 1*8*4*32=1024,   W02 1*2*8*32=512
#define WP10_OFF 0
#define WP01_OFF 27648
#define WP11_OFF (27648 + 6912)
#define WP00_OFF (27648 + 6912 + 13824)
#define WP02_OFF (27648 + 6912 + 13824 + 1024)
__device__ uint4 g_wperm[27648 + 6912 + 13824 + 1024 + 512];

// ---------------------------------------------------------------------------
__device__ __forceinline__ uint32_t f2tf32(float v) {
    uint32_t r;
    asm("cvt.rna.tf32.f32 %0, %1;" : "=r"(r) : "f"(v));
    return r;
}

__device__ __forceinline__ void mma_16n8k8(float* c, uint32_t a0, uint32_t a1,
                                           uint32_t a2, uint32_t a3,
                                           uint32_t b0, uint32_t b1) {
    asm volatile(
        "mma.sync.aligned.m16n8k8.row.col.f32.tf32.tf32.f32 "
        "{%0,%1,%2,%3}, {%4,%5,%6,%7}, {%8,%9}, {%0,%1,%2,%3};"
        : "+f"(c[0]), "+f"(c[1]), "+f"(c[2]), "+f"(c[3])
        : "r"(a0), "r"(a1), "r"(a2), "r"(a3), "r"(b0), "r"(b1));
}

// ---------------------------------------------------------------------------
// Weight permutation prep (R5 layout, KKT taps).
// ---------------------------------------------------------------------------
template <int CIN, int COUT, int KKT>
__global__ void k_permW(const float* __restrict__ W, uint4* __restrict__ dst)
{
    const int PAIRS = CIN / 16, NTS = COUT / 8;
    const int total = KKT * PAIRS * NTS * 32;
    const int s = blockIdx.x * 256 + threadIdx.x;
    if (s >= total) return;
    const int lane = s & 31;
    int t = s >> 5;
    const int nt = t % NTS; t /= NTS;
    const int pr = t % PAIRS; t /= PAIRS;
    const int k = t;
    const int four = lane & 3, grp = lane >> 2;
    const int col = nt * 8 + grp;
    const int r0 = pr * 16 + four;
    const size_t base = (size_t)k * CIN * COUT + col;
    uint4 v;
    v.x = f2tf32(W[base + (size_t)(r0)      * COUT]);
    v.y = f2tf32(W[base + (size_t)(r0 + 4)  * COUT]);
    v.z = f2tf32(W[base + (size_t)(r0 + 8)  * COUT]);
    v.w = f2tf32(W[base + (size_t)(r0 + 12) * COUT]);
    dst[s] = v;
}

// ---------------------------------------------------------------------------
// Unified sparse-conv GEMM via mma.sync tf32 (R5 inner loop).
// Block: 256 threads = 8 warps; 256 points/block; warp owns 32 points
// (two m16 tiles).  GATHER=1: 27-tap gather conv.  GATHER=0: 1x1 (KT=1).
// MODE 0: out[N,COUT] = relu(acc + b)
// MODE 1: out[N,128] cols [64,128) = acc + b + x[:,64:128)   (COUT=64)
// MODE 2: out[N,128] cols [0,64)   = acc + b + x[:,0:64)     (COUT=64)
// ---------------------------------------------------------------------------
template <int CIN, int COUT, int MODE, int GATHER>
__global__ __launch_bounds__(256) void k_conv_mma(
    const float* __restrict__ f, const int* __restrict__ nbr,
    const int* __restrict__ mask, const uint4* __restrict__ Wp,
    const float* __restrict__ b, const float* __restrict__ x,
    float* __restrict__ out)
{
    const int PAIRS = CIN / 16, NTS = COUT / 8;
    const int KT = GATHER ? KK : 1;
    __shared__ int   midx[GATHER ? 256 * KK : 8];
    __shared__ uint4 Bs4[CIN * COUT / 4];
    __shared__ float bs[COUT];

    const int tid  = threadIdx.x;
    const int warp = tid >> 5;
    const int lane = tid & 31;
    const int grp  = lane >> 2;
    const int four = lane & 3;

    if (tid < COUT) bs[tid] = b[tid];

    const int pbase = blockIdx.x * 256;
    if (GATHER) {
        for (int i = tid; i < 256 * KK; i += 256) {
            const int p = pbase + i / KK;
            int v = -1;
            if (p < NPTS) {
                const size_t g = (size_t)p * KK + (i % KK);
                if (mask[g] != 0) v = nbr[g];
            }
            midx[i] = v;
        }
    }

    const int lr = warp * 32 + grp;          // rows lr+{0,8,16,24}

    float acc0[NTS][4], acc1[NTS][4];
#pragma unroll
    for (int nt = 0; nt < NTS; nt++)
#pragma unroll
        for (int j = 0; j < 4; j++) { acc0[nt][j] = 0.f; acc1[nt][j] = 0.f; }

    const int slabN = PAIRS * NTS * 32;      // uint4 per k

    for (int k = 0; k < KT; k++) {
        __syncthreads();
        for (int i = tid; i < slabN; i += 256)
            Bs4[i] = Wp[(size_t)k * slabN + i];
        __syncthreads();

        int idx[4];
#pragma unroll
        for (int r = 0; r < 4; r++) {
            if (GATHER) {
                idx[r] = midx[(lr + r * 8) * KK + k];
            } else {
                const int p = pbase + lr + r * 8;
                idx[r] = (p < NPTS) ? p : (NPTS - 1);   // clamp; store guarded later
            }
        }
        const float* rows[4];
#pragma unroll
        for (int r = 0; r < 4; r++)
            rows[r] = f + (size_t)(idx[r] < 0 ? 0 : idx[r]) * CIN;

#pragma unroll
        for (int pr = 0; pr < PAIRS; pr++) {
            uint32_t A[4][4];   // [row][elem: four, four+4, four+8, four+12]
#pragma unroll
            for (int r = 0; r < 4; r++) {
                if (!GATHER || idx[r] >= 0) {
                    const float* rp = rows[r] + pr * 16 + four;
                    A[r][0] = f2tf32(__ldg(rp));
                    A[r][1] = f2tf32(__ldg(rp + 4));
                    A[r][2] = f2tf32(__ldg(rp + 8));
                    A[r][3] = f2tf32(__ldg(rp + 12));
                } else {
                    A[r][0] = A[r][1] = A[r][2] = A[r][3] = 0u;
                }
            }
#pragma unroll
            for (int nt = 0; nt < NTS; nt++) {
                const uint4 B = Bs4[(pr * NTS + nt) * 32 + lane];
                mma_16n8k8(acc0[nt], A[0][0], A[1][0], A[0][1], A[1][1], B.x, B.y);
                mma_16n8k8(acc0[nt], A[0][2], A[1][2], A[0][3], A[1][3], B.z, B.w);
                mma_16n8k8(acc1[nt], A[2][0], A[3][0], A[2][1], A[3][1], B.x, B.y);
                mma_16n8k8(acc1[nt], A[2][2], A[3][2], A[2][3], A[3][3], B.z, B.w);
            }
        }
    }

    // epilogue: acc0 -> rows lr, lr+8 ; acc1 -> rows lr+16, lr+24
#pragma unroll
    for (int t = 0; t < 2; t++) {
#pragma unroll
        for (int half = 0; half < 2; half++) {
            const int p = pbase + lr + t * 16 + half * 8;
            if (p >= NPTS) continue;
#pragma unroll
            for (int nt = 0; nt < NTS; nt++) {
                const float c0 = (t == 0) ? acc0[nt][half * 2]     : acc1[nt][half * 2];
                const float c1 = (t == 0) ? acc0[nt][half * 2 + 1] : acc1[nt][half * 2 + 1];
                const int col = nt * 8 + 2 * four;
                if (MODE == 0) {
                    float2 v = {fmaxf(c0 + bs[col], 0.f), fmaxf(c1 + bs[col + 1], 0.f)};
                    *reinterpret_cast<float2*>(out + (size_t)p * COUT + col) = v;
                } else {
                    const int oc = (MODE == 1) ? (64 + col) : col;
                    const size_t a = (size_t)p * 128 + oc;
                    float2 xr = *reinterpret_cast<const float2*>(x + a);
                    float2 v = {c0 + bs[col] + xr.x, c1 + bs[col + 1] + xr.y};
                    *reinterpret_cast<float2*>(out + a) = v;
                }
            }
        }
    }
}

// ---------------------------------------------------------------------------
extern "C" void kernel_launch(void* const* d_in, const int* in_sizes, int n_in,
                              void* d_out, int out_size)
{
    const float* x    = (const float*)d_in[0];
    const int*   nbr  = (const int*)  d_in[1];
    const int*   mask = (const int*)  d_in[2];   // bool -> int32 in harness
    const float* W00  = (const float*)d_in[3];
    const float* b00  = (const float*)d_in[4];
    const float* W01  = (const float*)d_in[5];
    const float* b01  = (const float*)d_in[6];
    const float* W02  = (const float*)d_in[7];
    const float* b02  = (const float*)d_in[8];
    const float* W10  = (const float*)d_in[9];
    const float* b10  = (const float*)d_in[10];
    const float* W11  = (const float*)d_in[11];
    const float* b11  = (const float*)d_in[12];
    float* out = (float*)d_out;

    float *h0, *h0c, *h1;
    uint4* wp;
    cudaGetSymbolAddress((void**)&h0,  g_h0);
    cudaGetSymbolAddress((void**)&h0c, g_h0c);
    cudaGetSymbolAddress((void**)&h1,  g_h1);
    cudaGetSymbolAddress((void**)&wp,  g_wperm);

    // weight permutation (tiny)
    k_permW<128, 32, KK><<<(27648 + 255) / 256, 256>>>(W10, wp + WP10_OFF);
    k_permW< 32, 32, KK><<<( 6912 + 255) / 256, 256>>>(W01, wp + WP01_OFF);
    k_permW< 32, 64, KK><<<(13824 + 255) / 256, 256>>>(W11, wp + WP11_OFF);
    k_permW<128, 32,  1><<<( 1024 + 255) / 256, 256>>>(W00, wp + WP00_OFF);
    k_permW< 32, 64,  1><<<(  512 + 255) / 256, 256>>>(W02, wp + WP02_OFF);

    const int blocks = (NPTS + 255) / 256;

    // branch 0: 1x1 -> relu  (mma, no gather)
    k_conv_mma<128, 32, 0, 0><<<blocks, 256>>>(x, nullptr, nullptr, wp + WP00_OFF, b00, nullptr, h0);
    // branch 1: 3x3 -> relu  (R5 gather loop)
    k_conv_mma<128, 32, 0, 1><<<blocks, 256>>>(x, nbr, mask, wp + WP10_OFF, b10, nullptr, h1);
    // branch 0: 3x3 -> relu
    k_conv_mma<32, 32, 0, 1><<<blocks, 256>>>(h0, nbr, mask, wp + WP01_OFF, b01, nullptr, h0c);
    // branch 0 tail: 1x1 + bias + residual -> out[:, 0:64)
    k_conv_mma<32, 64, 2, 0><<<blocks, 256>>>(h0c, nullptr, nullptr, wp + WP02_OFF, b02, x, out);
    // branch 1 tail: 3x3 + bias + residual -> out[:, 64:128)
    k_conv_mma<32, 64, 1, 1><<<blocks, 256>>>(h1, nbr, mask, wp + WP11_OFF, b11, x, out);
}